// round 1
// baseline (speedup 1.0000x reference)
#include <cuda_runtime.h>

#define NBINS   256
#define SUBBINS 4096            // 16 sub-bins per bin
#define APAR    0.07689350249903885f   // (1/255)^2 / (2*0.01^2)
#define FEPS    1e-10f
#define NB      4               // batch
#define HW      262144          // 512*512
#define S1_BLOCKS 32
#define S1_PIX    8192          // HW / S1_BLOCKS
#define S3_BLOCKS 64
#define S3_PIX    4096          // HW / S3_BLOCKS

// scratch (static device arrays — no runtime allocation)
__device__ float2 g_part[NB * S1_BLOCKS * SUBBINS];   // 4 MB partial (cnt, dev)
__device__ float  g_cdfn[NB * NBINS];

// transposed sub-bin index so stage-2 taps are LDS conflict-free
__device__ __forceinline__ int sub_idx(int s) { return ((s & 15) << 8) | (s >> 4); }

// ---------------- Stage 1: sub-bin count + first moment ----------------
__global__ __launch_bounds__(256) void stage1(const float* __restrict__ x) {
    __shared__ float2 sh[SUBBINS];          // 32 KB
    const int tid = threadIdx.x;
    for (int i = tid; i < SUBBINS; i += 256) sh[i] = make_float2(0.f, 0.f);
    __syncthreads();

    const int batch = blockIdx.y;
    const float4* xb = (const float4*)(x + (size_t)batch * HW + (size_t)blockIdx.x * S1_PIX);
    #pragma unroll
    for (int it = 0; it < S1_PIX / (256 * 4); it++) {
        float4 v = xb[tid + it * 256];
        float vals[4] = {v.x, v.y, v.z, v.w};
        #pragma unroll
        for (int q = 0; q < 4; q++) {
            float u = vals[q] * 255.0f;                 // bin-units position
            int s = (int)(u * 16.0f);
            s = min(s, SUBBINS - 1);
            float c = ((float)s + 0.5f) * 0.0625f;      // sub-bin center
            int idx = sub_idx(s);
            atomicAdd(&sh[idx].x, 1.0f);
            atomicAdd(&sh[idx].y, u - c);
        }
    }
    __syncthreads();
    float2* outp = g_part + (size_t)(batch * S1_BLOCKS + blockIdx.x) * SUBBINS;
    for (int i = tid; i < SUBBINS; i += 256) outp[i] = sh[i];
}

// ---------------- Stage 2: reduce -> hist (513-tap conv) -> scan -> cdfn ----------------
__global__ __launch_bounds__(256) void stage2() {
    __shared__ float2 comb[SUBBINS];        // 32 KB
    __shared__ float  wtab[513];
    __shared__ float  wdtab[513];
    __shared__ float  sc[NBINS];

    const int tid = threadIdx.x;
    const int batch = blockIdx.x;

    // combine 32 partials
    for (int i = tid; i < SUBBINS; i += 256) {
        float cn = 0.f, dv = 0.f;
        #pragma unroll
        for (int b = 0; b < S1_BLOCKS; b++) {
            float2 p = g_part[(size_t)(batch * S1_BLOCKS + b) * SUBBINS + i];
            cn += p.x; dv += p.y;
        }
        comb[i] = make_float2(cn, dv);
    }
    // tap tables: w(d) and w'(d), d = (k-255.5)/16 (bin units), same for all bins
    for (int k = tid; k < 513; k += 256) {
        float d = ((float)k - 255.5f) * 0.0625f;
        float w = __expf(-APAR * d * d);
        wtab[k]  = w;
        wdtab[k] = -2.0f * APAR * d * w;
    }
    __syncthreads();

    // hist[j] = sum over sub-bins in +-16 bins of cnt*w + dev*w'
    const int j = tid;
    float h = 0.f;
    const int sbase = 16 * j - 256;
    #pragma unroll 4
    for (int k = 0; k < 513; k++) {
        int s = sbase + k;
        if ((unsigned)s < (unsigned)SUBBINS) {
            float2 cd = comb[sub_idx(s)];   // consecutive across threads: conflict-free
            h = fmaf(cd.x, wtab[k], h);
            h = fmaf(cd.y, wdtab[k], h);
        }
    }

    // inclusive scan (Hillis-Steele)
    sc[tid] = h;
    __syncthreads();
    for (int off = 1; off < NBINS; off <<= 1) {
        float add = (tid >= off) ? sc[tid - off] : 0.f;
        __syncthreads();
        sc[tid] += add;
        __syncthreads();
    }
    float S    = sc[NBINS - 1];
    float invS = 1.0f / (S + FEPS);
    float cdf0 = sc[0] * invS;
    float cdfn = (sc[tid] * invS - cdf0) / (1.0f - cdf0 + FEPS);
    g_cdfn[batch * NBINS + tid] = cdfn;
}

// ---------------- Stage 3: per-pixel smoothing with replicated cdfn ----------------
__global__ __launch_bounds__(256) void stage3(const float* __restrict__ x,
                                              float* __restrict__ out) {
    __shared__ float rep[NBINS * 32];       // 32 KB: cdfn replicated per lane -> conflict-free
    const int tid  = threadIdx.x;
    const int batch = blockIdx.y;
    const float* cdfn = g_cdfn + batch * NBINS;
    for (int i = tid; i < NBINS * 32; i += 256) rep[i] = cdfn[i >> 5];
    __syncthreads();

    const int lane = tid & 31;
    const float G = __expf(-2.0f * APAR);   // step-ratio ratio

    const size_t ofs = (size_t)batch * HW + (size_t)blockIdx.x * S3_PIX;
    const float4* xb = (const float4*)(x + ofs);
    float4*       ob = (float4*)(out + ofs);

    #pragma unroll
    for (int it = 0; it < S3_PIX / (256 * 4); it++) {
        float4 v = xb[tid + it * 256];
        float vin[4] = {v.x, v.y, v.z, v.w};
        float vout[4];
        #pragma unroll
        for (int q = 0; q < 4; q++) {
            float u  = vin[q] * 255.0f;
            int   j0 = (int)u - 16;                 // u >= 0 -> trunc == floor
            float d0 = u - (float)j0;               // in [16,17)
            float w  = __expf(-APAR * d0 * d0);     // w(j0)
            float f  = __expf(APAR * (2.0f * d0 - 1.0f)); // step ratio
            float acc = 0.f, wsum = 0.f;
            #pragma unroll
            for (int k = 0; k < 33; k++) {
                int  jj = j0 + k;
                bool ok = ((unsigned)jj < 256u);
                int  jc = ok ? jj : 0;
                float val = rep[(jc << 5) + lane];  // bank == lane: conflict-free
                float wk  = ok ? w : 0.f;
                acc  = fmaf(wk, val, acc);
                wsum += wk;
                w *= f;                              // Gaussian recurrence
                f *= G;
            }
            vout[q] = __fdividef(acc, wsum + FEPS);
        }
        ob[tid + it * 256] = make_float4(vout[0], vout[1], vout[2], vout[3]);
    }
}

extern "C" void kernel_launch(void* const* d_in, const int* in_sizes, int n_in,
                              void* d_out, int out_size) {
    const float* x = (const float*)d_in[0];
    float* out = (float*)d_out;
    stage1<<<dim3(S1_BLOCKS, NB), 256>>>(x);
    stage2<<<NB, 256>>>();
    stage3<<<dim3(S3_BLOCKS, NB), 256>>>(x, out);
}

// round 2
// speedup vs baseline: 1.3437x; 1.3437x over previous
#include <cuda_runtime.h>

#define NBINS   256
#define SUBBINS 4096                  // 16 sub-bins per bin
#define APAR    0.07689350249903885f  // (1/255)^2 / (2*0.01^2)
#define GRATIO  0.8575538502216941f   // exp(-2*APAR)
#define FEPS    1e-10f
#define NB      4
#define HW      262144                // 512*512
#define GX      37                    // grid.x -> 37*4 = 148 blocks = 1/SM
#define NVEC    (HW / 4)              // float4 per batch

// scratch (static device arrays — no runtime allocation)
__device__ unsigned long long g_comb[NB * SUBBINS];  // packed cnt<<48 | devfield
__device__ float              g_cdfn[NB * NBINS];

// transposed sub-bin index: stage-2 taps (consecutive tid -> consecutive idx)
__device__ __forceinline__ int sub_idx(int s) { return ((s & 15) << 8) | (s >> 4); }

// ---------------- Stage 1: packed sub-bin count + first moment ----------------
// per-pixel packed u32: (1<<20) | (dev*2^14 + 2^13), dev in bin units, |dev|<=1/32
__global__ __launch_bounds__(256) void stage1(const float* __restrict__ x,
                                              unsigned long long* __restrict__ comb) {
    __shared__ unsigned int sh[SUBBINS];   // 16 KB
    const int tid = threadIdx.x;
    for (int i = tid; i < SUBBINS; i += 256) sh[i] = 0u;
    __syncthreads();

    const int batch = blockIdx.y;
    const float4* xb = (const float4*)(x + (size_t)batch * HW);
    for (int i = blockIdx.x * 256 + tid; i < NVEC; i += GX * 256) {
        float4 v = xb[i];
        float vals[4] = {v.x, v.y, v.z, v.w};
        #pragma unroll
        for (int q = 0; q < 4; q++) {
            float t = vals[q] * 4080.0f;          // u*16, u = x*255
            int s = min((int)t, SUBBINS - 1);
            float d16 = t - (float)s - 0.5f;      // 16*dev, in [-0.5, 0.5]
            // packed = (1<<20) + dev*2^14 + 2^13 ;  dev = d16/16
            float p = fmaf(d16, 1024.0f, 8192.0f);
            unsigned int val = 0x100000u + (unsigned int)p;
            atomicAdd(&sh[sub_idx(s)], val);
        }
    }
    __syncthreads();
    unsigned long long* cb = comb + batch * SUBBINS;
    for (int i = tid; i < SUBBINS; i += 256) {
        unsigned int v = sh[i];
        if (v) {
            unsigned long long w = ((unsigned long long)(v >> 20) << 48)
                                 | (unsigned long long)(v & 0xFFFFFu);
            atomicAdd(&cb[i], w);
        }
    }
}

// ---------------- Stage 2: decode -> hist (513-tap conv) -> scan -> cdfn ----------------
__global__ __launch_bounds__(256) void stage2(const unsigned long long* __restrict__ comb) {
    __shared__ float2 sm[SUBBINS];      // 32 KB (cnt, dev)
    __shared__ float  wtab[513];
    __shared__ float  wdtab[513];
    __shared__ float  sc[NBINS];

    const int tid = threadIdx.x;
    const int batch = blockIdx.x;

    for (int i = tid; i < SUBBINS; i += 256) {
        unsigned long long t = comb[batch * SUBBINS + i];
        float cnt = (float)(unsigned int)(t >> 48);
        long long df = (long long)(t & 0xFFFFFFFFFFFFull)
                     - ((long long)(t >> 48) << 13);     // remove per-pixel bias 2^13
        float dev = (float)df * 6.1035156e-5f;           // * 2^-14 -> bin units
        sm[i] = make_float2(cnt, dev);
    }
    for (int k = tid; k < 513; k += 256) {
        float d = ((float)k - 255.5f) * 0.0625f;
        float w = __expf(-APAR * d * d);
        wtab[k]  = w;
        wdtab[k] = -2.0f * APAR * d * w;
    }
    __syncthreads();

    const int j = tid;
    float h = 0.f;
    const int sbase = 16 * j - 256;
    #pragma unroll 4
    for (int k = 0; k < 513; k++) {
        int s = sbase + k;
        if ((unsigned)s < (unsigned)SUBBINS) {
            float2 cd = sm[sub_idx(s)];
            h = fmaf(cd.x, wtab[k], h);
            h = fmaf(cd.y, wdtab[k], h);
        }
    }

    sc[tid] = h;
    __syncthreads();
    for (int off = 1; off < NBINS; off <<= 1) {
        float add = (tid >= off) ? sc[tid - off] : 0.f;
        __syncthreads();
        sc[tid] += add;
        __syncthreads();
    }
    float S    = sc[NBINS - 1];
    float invS = 1.0f / (S + FEPS);
    float cdf0 = sc[0] * invS;
    g_cdfn[batch * NBINS + tid] = (sc[tid] * invS - cdf0) / (1.0f - cdf0 + FEPS);
}

// ---------------- Stage 3: per-pixel smoothing, padded replicated table ----------------
// table entry m (= j+16, j in [-16,272]): float2 {cdfn[j] or 0, valid ? 1 : 0}
// replicated x32 -> LDS.64 per lane, conflict-free, immediate offsets per tap
#define TROWS 289
__global__ __launch_bounds__(256) void stage3(const float* __restrict__ x,
                                              float* __restrict__ out) {
    extern __shared__ float2 rep[];     // TROWS*32 float2 = 73984 B
    const int tid   = threadIdx.x;
    const int batch = blockIdx.y;
    const float* cdfn = g_cdfn + batch * NBINS;
    for (int i = tid; i < TROWS * 32; i += 256) {
        int j = (i >> 5) - 16;
        bool ok = ((unsigned)j < 256u);
        rep[i] = make_float2(ok ? cdfn[j] : 0.f, ok ? 1.f : 0.f);
    }
    __syncthreads();

    const int lane = tid & 31;
    const float4* xb = (const float4*)(x   + (size_t)batch * HW);
    float4*       ob = (float4*)      (out + (size_t)batch * HW);

    for (int i = blockIdx.x * 256 + tid; i < NVEC; i += GX * 256) {
        float4 v = xb[i];
        float vin[4] = {v.x, v.y, v.z, v.w};
        float w[4], f[4], acc[4], ws[4];
        int   bix[4];
        #pragma unroll
        for (int q = 0; q < 4; q++) {
            float t  = vin[q] * 255.0f;
            int   fl = (int)t;                    // floor (t >= 0)
            float d0 = (t - (float)fl) + 16.0f;   // u - j0, in [16,17)
            w[q] = __expf(-APAR * d0 * d0);
            f[q] = __expf(fmaf(2.0f * APAR, d0, -APAR));
            bix[q] = (fl << 5) + lane;            // table row fl = j0+16
            acc[q] = 0.f; ws[q] = 0.f;
        }
        #pragma unroll
        for (int k = 0; k < 33; k++) {
            #pragma unroll
            for (int q = 0; q < 4; q++) {
                float2 cv = rep[bix[q] + (k << 5)];
                acc[q] = fmaf(w[q], cv.x, acc[q]);
                ws[q]  = fmaf(w[q], cv.y, ws[q]);
                w[q] *= f[q];
                f[q] *= GRATIO;
            }
        }
        float vout[4];
        #pragma unroll
        for (int q = 0; q < 4; q++)
            vout[q] = __fdividef(acc[q], ws[q] + FEPS);
        ob[i] = make_float4(vout[0], vout[1], vout[2], vout[3]);
    }
}

extern "C" void kernel_launch(void* const* d_in, const int* in_sizes, int n_in,
                              void* d_out, int out_size) {
    const float* x = (const float*)d_in[0];
    float* out = (float*)d_out;

    void* combp = nullptr;
    cudaGetSymbolAddress(&combp, g_comb);
    cudaMemsetAsync(combp, 0, sizeof(unsigned long long) * NB * SUBBINS, 0);

    cudaFuncSetAttribute(stage3, cudaFuncAttributeMaxDynamicSharedMemorySize,
                         TROWS * 32 * sizeof(float2));

    stage1<<<dim3(GX, NB), 256>>>(x, (unsigned long long*)combp);
    stage2<<<NB, 256>>>((const unsigned long long*)combp);
    stage3<<<dim3(GX, NB), 256, TROWS * 32 * sizeof(float2)>>>(x, out);
}

// round 6
// speedup vs baseline: 2.0161x; 1.5004x over previous
#include <cuda_runtime.h>

#define NBINS   256
#define SUBBINS 4096
#define APAR    0.07689350249903885f  // (1/255)^2 / (2*0.01^2)
#define GRATIO  0.85745463520f        // exp(-2*APAR)
#define FEPS    1e-10f
#define NB      4
#define HW      262144
#define NVEC    (HW / 4)
#define GRID    148
#define GPB     37                    // blocks per batch
#define TAPS    27                    // +-13 bins
#define TROWS   282                   // rows j in [-13, 268]
#define SMEMB   (TROWS * 32 * 8)      // 72192 B dynamic smem

// persistent scratch (zero-init at load; invariants restored in-kernel)
__device__ unsigned long long g_comb[NB * SUBBINS];   // NATURAL sub-bin order
__device__ float              g_hist[NB * NBINS];
__device__ float              g_cdfn[NB * NBINS];
__device__ unsigned int       g_bar;     // monotonic arrival counter
__device__ unsigned int       g_epoch;   // g_bar value at launch start

// transposed smem slot for conflict spreading in P1
__device__ __forceinline__ int sub_idx(int s) { return ((s & 15) << 8) | (s >> 4); }

__device__ __forceinline__ void gbar(unsigned target) {
    __syncthreads();
    if (threadIdx.x == 0) {
        __threadfence();
        atomicAdd(&g_bar, 1u);
        unsigned v;
        do {
            asm volatile("ld.global.acquire.gpu.b32 %0, [%1];"
                         : "=r"(v) : "l"(&g_bar) : "memory");
        } while (v < target);
    }
    __syncthreads();
}

__global__ __launch_bounds__(256, 1) void fused(const float* __restrict__ x,
                                                float* __restrict__ out) {
    extern __shared__ __align__(16) unsigned char dynsm[];
    unsigned* shu = (unsigned*)dynsm;        // P1: 16 KB
    float*    scn = (float*)dynsm;           // P3: 1 KB
    float2*   rep = (float2*)dynsm;          // P5: 72 KB

    const int tid   = threadIdx.x;
    const int bid   = blockIdx.x;
    const int lane  = tid & 31;
    const int warp  = tid >> 5;
    const int batch = bid / GPB;
    const int sub   = bid % GPB;

    __shared__ unsigned s_ep;
    if (tid == 0) s_ep = g_epoch;

    // ---- P1: packed sub-bin histogram (count + first moment) ----
    for (int i = tid; i < SUBBINS; i += 256) shu[i] = 0u;
    __syncthreads();
    const unsigned ep = s_ep;

    const float4* xb = (const float4*)(x + (size_t)batch * HW);
    for (int i = sub * 256 + tid; i < NVEC; i += GPB * 256) {
        float4 v = xb[i];
        float vals[4] = {v.x, v.y, v.z, v.w};
        #pragma unroll
        for (int q = 0; q < 4; q++) {
            float t = vals[q] * 4080.0f;            // u*16
            int s = min((int)t, SUBBINS - 1);
            float d16 = t - (float)s - 0.5f;        // 16*dev in [-0.5,0.5]
            unsigned val = 0x100000u + (unsigned)fmaf(d16, 1024.0f, 8192.0f);
            atomicAdd(&shu[sub_idx(s)], val);
        }
    }
    __syncthreads();
    // flush: smem slot i holds sub-bin s = inv(i); store g_comb in NATURAL order
    for (int i = tid; i < SUBBINS; i += 256) {
        unsigned v = shu[i];
        if (v) {
            int s = ((i & 255) << 4) | (i >> 8);    // inverse of sub_idx
            unsigned long long w = ((unsigned long long)(v >> 20) << 48)
                                 | (unsigned long long)(v & 0xFFFFFu);
            atomicAdd(&g_comb[batch * SUBBINS + s], w);
        }
    }
    gbar(ep + GRID);

    // ---- P2: conv -> hist (one warp per bin, +-14 bins of sub-bin taps) ----
    {
        int wg = bid * 8 + warp;
        if (wg < NB * NBINS) {
            int b = wg >> 8, j = wg & 255;
            float h = 0.f;
            int sbase = 16 * j - 224 + lane;
            #pragma unroll
            for (int t = 0; t < 14; t++) {
                int s = sbase + t * 32;
                if ((unsigned)s < (unsigned)SUBBINS) {
                    unsigned long long cw = __ldcg(&g_comb[b * SUBBINS + s]);
                    float cnt = (float)(unsigned)(cw >> 48);
                    long long df = (long long)(cw & 0xFFFFFFFFFFFFull)
                                 - ((long long)(cw >> 48) << 13);
                    float dev = (float)df * 6.1035156e-5f;   // 2^-14
                    float d = ((float)s + 0.5f) * 0.0625f - (float)j;
                    float w = __expf(-APAR * d * d);
                    h = fmaf(cnt, w, h);
                    h = fmaf(dev, -2.0f * APAR * d * w, h);
                }
            }
            #pragma unroll
            for (int o = 16; o; o >>= 1) h += __shfl_xor_sync(0xFFFFFFFFu, h, o);
            if (lane == 0) g_hist[wg] = h;
        }
    }
    gbar(ep + 2 * GRID);

    // ---- P3: scan + cdf normalize (blocks 0..3); others re-zero g_comb ----
    if (bid < NB) {
        scn[tid] = __ldcg(&g_hist[bid * NBINS + tid]);
        __syncthreads();
        for (int off = 1; off < NBINS; off <<= 1) {
            float add = (tid >= off) ? scn[tid - off] : 0.f;
            __syncthreads();
            scn[tid] += add;
            __syncthreads();
        }
        float S = scn[NBINS - 1];
        float invS = 1.0f / (S + FEPS);
        float c0 = scn[0] * invS;
        g_cdfn[bid * NBINS + tid] = (scn[tid] * invS - c0) / (1.0f - c0 + FEPS);
    } else {
        int rb = bid - NB;                           // 144 blocks clear 16K words
        for (int p = rb * 256 + tid; p < NB * SUBBINS; p += (GRID - NB) * 256)
            g_comb[p] = 0ull;
    }
    gbar(ep + 3 * GRID);

    // ---- P5: per-pixel 27-tap smoothing, replicated {cdfn,valid} table ----
    {
        const float* cdfn = g_cdfn + (batch << 8);
        for (int i = tid; i < TROWS * 32; i += 256) {
            int j = (i >> 5) - 13;
            bool ok = ((unsigned)j < 256u);
            rep[i] = make_float2(ok ? __ldcg(cdfn + j) : 0.f,
                                 ok ? 1.f : 0.f);
        }
        __syncthreads();

        float4* ob = (float4*)(out + (size_t)batch * HW);
        for (int i = sub * 256 + tid; i < NVEC; i += GPB * 256) {
            float4 v = xb[i];
            float vin[4] = {v.x, v.y, v.z, v.w};
            float w[4], f[4], acc[4], ws[4];
            const float2* base[4];
            #pragma unroll
            for (int q = 0; q < 4; q++) {
                float u  = vin[q] * 255.0f;
                int   fl = (int)u;                    // floor (u >= 0)
                float d0 = (u - (float)fl) + 13.0f;   // in [13,14)
                w[q] = __expf(-APAR * d0 * d0);
                f[q] = __expf(fmaf(2.0f * APAR, d0, -APAR));
                base[q] = rep + (fl << 5) + lane;     // row fl = j0+13
                acc[q] = 0.f; ws[q] = 0.f;
            }
            #pragma unroll
            for (int k = 0; k < TAPS; k++) {
                #pragma unroll
                for (int q = 0; q < 4; q++) {
                    float2 cv = base[q][k << 5];
                    acc[q] = fmaf(w[q], cv.x, acc[q]);
                    ws[q]  = fmaf(w[q], cv.y, ws[q]);
                    w[q] *= f[q];
                    f[q] *= GRATIO;
                }
            }
            float4 o;
            o.x = __fdividef(acc[0], ws[0] + FEPS);
            o.y = __fdividef(acc[1], ws[1] + FEPS);
            o.z = __fdividef(acc[2], ws[2] + FEPS);
            o.w = __fdividef(acc[3], ws[3] + FEPS);
            ob[i] = o;
        }
    }

    if (bid == 0 && tid == 0) g_epoch = ep + 3 * GRID;
}

extern "C" void kernel_launch(void* const* d_in, const int* in_sizes, int n_in,
                              void* d_out, int out_size) {
    const float* x = (const float*)d_in[0];
    float* out = (float*)d_out;
    cudaFuncSetAttribute(fused, cudaFuncAttributeMaxDynamicSharedMemorySize, SMEMB);
    fused<<<GRID, 256, SMEMB>>>(x, out);
}

// round 7
// speedup vs baseline: 2.1713x; 1.0770x over previous
#include <cuda_runtime.h>

#define NBINS   256
#define SUBBINS 4096
#define APAR    0.07689350249903885f  // (1/255)^2 / (2*0.01^2)
#define GRATIO  0.85745463520f        // exp(-2*APAR)
#define FEPS    1e-10f
#define NB      4
#define HW      262144
#define NVEC    (HW / 4)
#define GRID    148
#define GPB     37                    // blocks per batch
#define NT      512                   // threads per block
#define TAPS    27                    // +-13 bins
#define TROWS   282                   // rows j in [-13, 268]
// smem: rep 9024 f | e0 513 | e1 513 | scn 256 | shu 4096 u32
#define SM_REP  0
#define SM_E0   9024
#define SM_E1   9537
#define SM_SCN  10050
#define SM_SHU  10306
#define SMEMB   ((10306 + 4096) * 4)

// persistent scratch (zero-init at load; invariants restored in-kernel)
__device__ unsigned long long g_comb[NB * SUBBINS];   // NATURAL sub-bin order
__device__ float              g_hist[NB * NBINS];
__device__ float              g_cdfn[NB * NBINS];
__device__ unsigned int       g_bar;
__device__ unsigned int       g_epoch;

// transposed smem slot for conflict spreading in P1
__device__ __forceinline__ int sub_idx(int s) { return ((s & 15) << 8) | (s >> 4); }

__device__ __forceinline__ void gbar(unsigned target) {
    __syncthreads();
    if (threadIdx.x == 0) {
        __threadfence();
        atomicAdd(&g_bar, 1u);
        unsigned v;
        do {
            asm volatile("ld.global.acquire.gpu.b32 %0, [%1];"
                         : "=r"(v) : "l"(&g_bar) : "memory");
        } while (v < target);
    }
    __syncthreads();
}

__global__ __launch_bounds__(NT, 1) void fused(const float* __restrict__ x,
                                               float* __restrict__ out) {
    extern __shared__ __align__(16) float smf[];
    float*    rep = smf + SM_REP;
    float*    e0  = smf + SM_E0;
    float*    e1  = smf + SM_E1;
    float*    scn = smf + SM_SCN;
    unsigned* shu = (unsigned*)(smf + SM_SHU);

    const int tid   = threadIdx.x;
    const int bid   = blockIdx.x;
    const int lane  = tid & 31;
    const int warp  = tid >> 5;
    const int batch = bid / GPB;
    const int sub   = bid % GPB;

    __shared__ unsigned s_ep;
    if (tid == 0) s_ep = g_epoch;

    // ---- P0: edge ws tables (data-independent; ready by P5) ----
    for (int i = tid; i < 1026; i += NT) {
        bool hi = (i >= 513);
        int  m  = hi ? (i - 513) : i;
        float u = (hi ? 240.0f : 0.0f) + (float)m * 0.03125f;
        int   fl = (int)u;
        float d0 = (u - (float)fl) + 13.0f;
        float w = __expf(-APAR * d0 * d0);
        float f = __expf(fmaf(2.0f * APAR, d0, -APAR));
        float ws = 0.f;
        #pragma unroll
        for (int k = 0; k < TAPS; k++) {
            int j = fl - 13 + k;
            if ((unsigned)j < 256u) ws += w;
            w *= f;
            f *= GRATIO;
        }
        (hi ? e1 : e0)[m] = ws;
    }

    // ---- P1: packed sub-bin histogram (count + first moment) ----
    for (int i = tid; i < SUBBINS; i += NT) shu[i] = 0u;
    __syncthreads();
    const unsigned ep = s_ep;

    const float4* xb = (const float4*)(x + (size_t)batch * HW);
    for (int i = sub * NT + tid; i < NVEC; i += GPB * NT) {
        float4 v = xb[i];
        float vals[4] = {v.x, v.y, v.z, v.w};
        #pragma unroll
        for (int q = 0; q < 4; q++) {
            float t = vals[q] * 4080.0f;            // u*16
            int s = min((int)t, SUBBINS - 1);
            float d16 = t - (float)s - 0.5f;        // 16*dev in [-0.5,0.5]
            unsigned val = 0x100000u + (unsigned)fmaf(d16, 1024.0f, 8192.0f);
            atomicAdd(&shu[sub_idx(s)], val);
        }
    }
    __syncthreads();
    for (int i = tid; i < SUBBINS; i += NT) {
        unsigned v = shu[i];
        if (v) {
            int s = ((i & 255) << 4) | (i >> 8);    // inverse of sub_idx
            unsigned long long w = ((unsigned long long)(v >> 20) << 48)
                                 | (unsigned long long)(v & 0xFFFFFu);
            atomicAdd(&g_comb[batch * SUBBINS + s], w);
        }
    }
    gbar(ep + GRID);

    // ---- P2: conv -> hist (one warp per bin) ----
    {
        int wg = bid * 16 + warp;
        if (wg < NB * NBINS) {
            int b = wg >> 8, j = wg & 255;
            float h = 0.f;
            int sbase = 16 * j - 224 + lane;
            #pragma unroll
            for (int t = 0; t < 14; t++) {
                int s = sbase + t * 32;
                if ((unsigned)s < (unsigned)SUBBINS) {
                    unsigned long long cw = __ldcg(&g_comb[b * SUBBINS + s]);
                    float cnt = (float)(unsigned)(cw >> 48);
                    long long df = (long long)(cw & 0xFFFFFFFFFFFFull)
                                 - ((long long)(cw >> 48) << 13);
                    float dev = (float)df * 6.1035156e-5f;   // 2^-14
                    float d = ((float)s + 0.5f) * 0.0625f - (float)j;
                    float w = __expf(-APAR * d * d);
                    h = fmaf(cnt, w, h);
                    h = fmaf(dev, -2.0f * APAR * d * w, h);
                }
            }
            #pragma unroll
            for (int o = 16; o; o >>= 1) h += __shfl_xor_sync(0xFFFFFFFFu, h, o);
            if (lane == 0) g_hist[wg] = h;
        }
    }
    gbar(ep + 2 * GRID);

    // ---- P3: scan + cdf normalize (blocks 0..3); others re-zero g_comb ----
    if (bid < NB) {
        if (tid < NBINS) scn[tid] = __ldcg(&g_hist[bid * NBINS + tid]);
        __syncthreads();
        for (int off = 1; off < NBINS; off <<= 1) {
            float add = (tid < NBINS && tid >= off) ? scn[tid - off] : 0.f;
            __syncthreads();
            if (tid < NBINS) scn[tid] += add;
            __syncthreads();
        }
        if (tid < NBINS) {
            float S = scn[NBINS - 1];
            float invS = 1.0f / (S + FEPS);
            float c0 = scn[0] * invS;
            g_cdfn[bid * NBINS + tid] = (scn[tid] * invS - c0) / (1.0f - c0 + FEPS);
        }
    } else {
        int rb = bid - NB;
        for (int p = rb * NT + tid; p < NB * SUBBINS; p += (GRID - NB) * NT)
            g_comb[p] = 0ull;
    }
    gbar(ep + 3 * GRID);

    // ---- P5: per-pixel 27-tap smoothing, zero-padded replicated float table ----
    {
        const float* cdfn = g_cdfn + (batch << 8);
        for (int i = tid; i < TROWS * 32; i += NT) {
            int j = (i >> 5) - 13;
            rep[i] = ((unsigned)j < 256u) ? __ldcg(cdfn + j) : 0.f;
        }
        __syncthreads();
        const float wsI = e0[512];   // interior weight-sum (constant to ~1e-7)

        float4* ob = (float4*)(out + (size_t)batch * HW);
        for (int i = sub * NT + tid; i < NVEC; i += GPB * NT) {
            float4 v = xb[i];
            float vin[4] = {v.x, v.y, v.z, v.w};
            float u[4], w[4], f[4], acc[4];
            const float* base[4];
            #pragma unroll
            for (int q = 0; q < 4; q++) {
                u[q] = vin[q] * 255.0f;
                int   fl = (int)u[q];                 // floor (u >= 0)
                float d0 = (u[q] - (float)fl) + 13.0f;
                w[q] = __expf(-APAR * d0 * d0);
                f[q] = __expf(fmaf(2.0f * APAR, d0, -APAR));
                base[q] = rep + (fl << 5) + lane;
                acc[q] = 0.f;
            }
            #pragma unroll
            for (int k = 0; k < TAPS; k++) {
                #pragma unroll
                for (int q = 0; q < 4; q++) {
                    acc[q] = fmaf(w[q], base[q][k << 5], acc[q]);
                    w[q] *= f[q];
                    f[q] *= GRATIO;
                }
            }
            float vout[4];
            #pragma unroll
            for (int q = 0; q < 4; q++) {
                float wsq;
                if (u[q] < 16.0f) {
                    float p = u[q] * 32.0f;
                    int ii = (int)p; float fr = p - (float)ii;
                    float a = e0[ii];
                    wsq = fmaf(fr, e0[ii + 1] - a, a);
                } else if (u[q] >= 240.0f) {
                    float p = (u[q] - 240.0f) * 32.0f;
                    int ii = (int)p; float fr = p - (float)ii;
                    float a = e1[ii];
                    wsq = fmaf(fr, e1[ii + 1] - a, a);
                } else {
                    wsq = wsI;
                }
                vout[q] = __fdividef(acc[q], wsq + FEPS);
            }
            ob[i] = make_float4(vout[0], vout[1], vout[2], vout[3]);
        }
    }

    if (bid == 0 && tid == 0) g_epoch = ep + 3 * GRID;
}

extern "C" void kernel_launch(void* const* d_in, const int* in_sizes, int n_in,
                              void* d_out, int out_size) {
    const float* x = (const float*)d_in[0];
    float* out = (float*)d_out;
    cudaFuncSetAttribute(fused, cudaFuncAttributeMaxDynamicSharedMemorySize, SMEMB);
    fused<<<GRID, NT, SMEMB>>>(x, out);
}

// round 8
// speedup vs baseline: 2.8812x; 1.3269x over previous
#include <cuda_runtime.h>

#define NBINS   256
#define SUBBINS 4096
#define APAR    0.07689350249903885f  // (1/255)^2 / (2*0.01^2)
#define GRATIO  0.85745463520f        // exp(-2*APAR)
#define FEPS    1e-10f
#define NB      4
#define HW      262144
#define NVEC    (HW / 4)
#define GRID    148
#define GPB     37                    // blocks per batch
#define NT      512                   // threads per block
#define TAPS    27                    // +-13 bins
#define TPTS    8192                  // g-table points (1/32 bin)
// smem floats: gtab 8192 (aliases shu 4096 u32) | cdp 288 | scn 256
#define SM_GTAB 0
#define SM_CDP  8192
#define SM_SCN  8480
#define SMEMB   ((8480 + 256) * 4)

// persistent scratch (zero-init at load; invariants restored in-kernel)
__device__ unsigned long long g_comb[NB * SUBBINS];   // NATURAL sub-bin order
__device__ float              g_hist[NB * NBINS];
__device__ float              g_cdfn[NB * NBINS];
__device__ unsigned int       g_bar;
__device__ unsigned int       g_epoch;

// transposed smem slot for conflict spreading in P1
__device__ __forceinline__ int sub_idx(int s) { return ((s & 15) << 8) | (s >> 4); }

__device__ __forceinline__ void gbar(unsigned target) {
    __syncthreads();
    if (threadIdx.x == 0) {
        __threadfence();
        atomicAdd(&g_bar, 1u);
        unsigned v;
        do {
            asm volatile("ld.global.acquire.gpu.b32 %0, [%1];"
                         : "=r"(v) : "l"(&g_bar) : "memory");
        } while (v < target);
    }
    __syncthreads();
}

__global__ __launch_bounds__(NT, 1) void fused(const float* __restrict__ x,
                                               float* __restrict__ out) {
    extern __shared__ __align__(16) float smf[];
    float*    gtab = smf + SM_GTAB;
    float*    cdp  = smf + SM_CDP;            // zero-padded cdfn, rows j in [-13,274]
    float*    scn  = smf + SM_SCN;
    unsigned* shu  = (unsigned*)(smf + SM_GTAB);  // P1 alias (dead before gtab build)

    const int tid   = threadIdx.x;
    const int bid   = blockIdx.x;
    const int lane  = tid & 31;
    const int warp  = tid >> 5;
    const int batch = bid / GPB;
    const int sub   = bid % GPB;

    __shared__ unsigned s_ep;
    if (tid == 0) s_ep = g_epoch;

    // ---- P1: packed sub-bin histogram (count + first moment) ----
    for (int i = tid; i < SUBBINS; i += NT) shu[i] = 0u;
    __syncthreads();
    const unsigned ep = s_ep;

    const float4* xb = (const float4*)(x + (size_t)batch * HW);
    for (int i = sub * NT + tid; i < NVEC; i += GPB * NT) {
        float4 v = xb[i];
        float vals[4] = {v.x, v.y, v.z, v.w};
        #pragma unroll
        for (int q = 0; q < 4; q++) {
            float t = vals[q] * 4080.0f;            // u*16
            int s = min((int)t, SUBBINS - 1);
            float d16 = t - (float)s - 0.5f;        // 16*dev in [-0.5,0.5]
            unsigned val = 0x100000u + (unsigned)fmaf(d16, 1024.0f, 8192.0f);
            atomicAdd(&shu[sub_idx(s)], val);
        }
    }
    __syncthreads();
    for (int i = tid; i < SUBBINS; i += NT) {
        unsigned v = shu[i];
        if (v) {
            int s = ((i & 255) << 4) | (i >> 8);    // inverse of sub_idx
            unsigned long long w = ((unsigned long long)(v >> 20) << 48)
                                 | (unsigned long long)(v & 0xFFFFFu);
            atomicAdd(&g_comb[batch * SUBBINS + s], w);
        }
    }
    gbar(ep + GRID);

    // ---- P2: conv -> hist (one warp per bin) ----
    {
        int wg = bid * 16 + warp;
        if (wg < NB * NBINS) {
            int b = wg >> 8, j = wg & 255;
            float h = 0.f;
            int sbase = 16 * j - 224 + lane;
            #pragma unroll
            for (int t = 0; t < 14; t++) {
                int s = sbase + t * 32;
                if ((unsigned)s < (unsigned)SUBBINS) {
                    unsigned long long cw = __ldcg(&g_comb[b * SUBBINS + s]);
                    float cnt = (float)(unsigned)(cw >> 48);
                    long long df = (long long)(cw & 0xFFFFFFFFFFFFull)
                                 - ((long long)(cw >> 48) << 13);
                    float dev = (float)df * 6.1035156e-5f;   // 2^-14
                    float d = ((float)s + 0.5f) * 0.0625f - (float)j;
                    float w = __expf(-APAR * d * d);
                    h = fmaf(cnt, w, h);
                    h = fmaf(dev, -2.0f * APAR * d * w, h);
                }
            }
            #pragma unroll
            for (int o = 16; o; o >>= 1) h += __shfl_xor_sync(0xFFFFFFFFu, h, o);
            if (lane == 0) g_hist[wg] = h;
        }
    }
    gbar(ep + 2 * GRID);

    // ---- P3: scan + cdf normalize (blocks 0..3); others re-zero g_comb ----
    if (bid < NB) {
        if (tid < NBINS) scn[tid] = __ldcg(&g_hist[bid * NBINS + tid]);
        __syncthreads();
        for (int off = 1; off < NBINS; off <<= 1) {
            float add = (tid < NBINS && tid >= off) ? scn[tid - off] : 0.f;
            __syncthreads();
            if (tid < NBINS) scn[tid] += add;
            __syncthreads();
        }
        if (tid < NBINS) {
            float S = scn[NBINS - 1];
            float invS = 1.0f / (S + FEPS);
            float c0 = scn[0] * invS;
            g_cdfn[bid * NBINS + tid] = (scn[tid] * invS - c0) / (1.0f - c0 + FEPS);
        }
    } else {
        int rb = bid - NB;
        for (int p = rb * NT + tid; p < NB * SUBBINS; p += (GRID - NB) * NT)
            g_comb[p] = 0ull;
    }
    gbar(ep + 3 * GRID);

    // ---- P4: build this batch's 8192-pt g-table in smem (per block) ----
    {
        const float* cdfn = g_cdfn + (batch << 8);
        for (int i = tid; i < 288; i += NT) {
            int j = i - 13;
            cdp[i] = ((unsigned)j < 256u) ? __ldcg(cdfn + j) : 0.f;
        }
        __syncthreads();
        #pragma unroll
        for (int it = 0; it < TPTS / NT; it++) {
            int   m  = it * NT + tid;
            int   fl = m >> 5;                      // all lanes in warp share fl
            float d0 = (float)(m & 31) * 0.03125f + 13.0f;
            float w  = __expf(-APAR * d0 * d0);
            float f  = __expf(fmaf(2.0f * APAR, d0, -APAR));
            float acc = 0.f, ws = 0.f;
            #pragma unroll
            for (int k = 0; k < TAPS; k++) {
                int jj = fl - 13 + k;
                acc = fmaf(w, cdp[jj + 13], acc);   // broadcast LDS
                ws += ((unsigned)jj < 256u) ? w : 0.f;
                w *= f;
                f *= GRATIO;
            }
            gtab[m] = __fdividef(acc, ws + FEPS);
        }
        __syncthreads();
    }

    // ---- P5: per-pixel linear interpolation ----
    {
        float4* ob = (float4*)(out + (size_t)batch * HW);
        for (int i = sub * NT + tid; i < NVEC; i += GPB * NT) {
            float4 v = xb[i];
            float4 o;
            float t; int ix; float fr, lo;
            t = v.x * 8160.0f; ix = (int)t; fr = t - (float)ix;
            lo = gtab[ix]; o.x = fmaf(fr, gtab[ix + 1] - lo, lo);
            t = v.y * 8160.0f; ix = (int)t; fr = t - (float)ix;
            lo = gtab[ix]; o.y = fmaf(fr, gtab[ix + 1] - lo, lo);
            t = v.z * 8160.0f; ix = (int)t; fr = t - (float)ix;
            lo = gtab[ix]; o.z = fmaf(fr, gtab[ix + 1] - lo, lo);
            t = v.w * 8160.0f; ix = (int)t; fr = t - (float)ix;
            lo = gtab[ix]; o.w = fmaf(fr, gtab[ix + 1] - lo, lo);
            ob[i] = o;
        }
    }

    if (bid == 0 && tid == 0) g_epoch = ep + 3 * GRID;
}

extern "C" void kernel_launch(void* const* d_in, const int* in_sizes, int n_in,
                              void* d_out, int out_size) {
    const float* x = (const float*)d_in[0];
    float* out = (float*)d_out;
    cudaFuncSetAttribute(fused, cudaFuncAttributeMaxDynamicSharedMemorySize, SMEMB);
    fused<<<GRID, NT, SMEMB>>>(x, out);
}